// round 10
// baseline (speedup 1.0000x reference)
#include <cuda_runtime.h>
#include <cuda_bf16.h>

#define BB   8
#define NN   32768
#define KK   20
#define CHN  16
#define NPTS (BB * 32768)

__device__ int g_idx_shift;  // 1 -> idx is int64, 0 -> int32

// Parallel width detect: odd 32-bit words all zero <=> little-endian int64.
__global__ void detect_idx_kernel(const unsigned int* __restrict__ idx32) {
    unsigned int any = idx32[2 * threadIdx.x + 1] | idx32[2 * threadIdx.x + 257];
    any = __ballot_sync(0xffffffffu, any != 0);
    __shared__ unsigned int warp_any[4];
    if ((threadIdx.x & 31) == 0) warp_any[threadIdx.x >> 5] = any;
    __syncthreads();
    if (threadIdx.x == 0)
        g_idx_shift = ((warp_any[0] | warp_any[1] | warp_any[2] | warp_any[3]) == 0) ? 1 : 0;
}

#define L2E 1.44269504088896f   // log2(e)
#define ZSH 20.0f               // fixed softmax shift (range guard, shift-invariant)

// 8 lanes per point: lane = (hi, q). Per iteration kp: lanes hi=0 compute
// k=2kp, hi=1 compute k=2kp+1; q = channel quarter. Each lane gathers its own
// xv (duplicates across q merge in-wavefront), eo[4] is exactly its 16B store
// chunk -> warp STG.128 covers 4 FULL 128B lines. No broadcast shuffles.
__global__ void __launch_bounds__(128, 8)
gap_kernel(const float* __restrict__ x,
           const int*   __restrict__ idx32,
           const float* __restrict__ w1,  const float* __restrict__ g1,
           const float* __restrict__ b1,  const float* __restrict__ m1,
           const float* __restrict__ v1,
           const float* __restrict__ w2,  const float* __restrict__ g2,
           const float* __restrict__ b2,  const float* __restrict__ m2,
           const float* __restrict__ v2,
           const float* __restrict__ w1n, const float* __restrict__ g1n,
           const float* __restrict__ b1n, const float* __restrict__ m1n,
           const float* __restrict__ v1n,
           const float* __restrict__ w2n, const float* __restrict__ g2n,
           const float* __restrict__ b2n, const float* __restrict__ m2n,
           const float* __restrict__ v2n,
           float* __restrict__ out, float* __restrict__ edge_o)
{
    // ---- fold BN into affine constants ----
    __shared__ float sA1[CHN], sB1[CHN], sC1[CHN], sW2[CHN];
    __shared__ float sAn[CHN], sBn[CHN], sCn[CHN], sWn[CHN];
    __shared__ float sZC;

    int t = threadIdx.x;
    if (t < CHN) {
        float s1 = g1[t] * rsqrtf(v1[t] + 1e-5f);
        sA1[t] = w1[2*t]     * s1;
        sB1[t] = w1[2*t + 1] * s1;
        sC1[t] = b1[t] - m1[t] * s1;
        float s2 = g2[0] * rsqrtf(v2[0] + 1e-5f);
        sW2[t] = w2[t] * s2;

        float s1n = g1n[t] * rsqrtf(v1n[t] + 1e-5f);
        sAn[t] = w1n[2*t]     * s1n;
        sBn[t] = w1n[2*t + 1] * s1n;
        sCn[t] = b1n[t] - m1n[t] * s1n;
        float s2n = g2n[0] * rsqrtf(v2n[0] + 1e-5f);
        sWn[t] = w2n[t] * s2n;

        if (t == 0) {
            float c2  = b2[0]  - m2[0]  * (g2[0]  * rsqrtf(v2[0]  + 1e-5f));
            float c2n = b2n[0] - m2n[0] * (g2n[0] * rsqrtf(v2n[0] + 1e-5f));
            sZC = c2 + c2n;
        }
    }
    __syncthreads();

    int g   = blockIdx.x * 128 + t;
    int p   = g >> 3;                   // point id (8 lanes per point)
    int l8  = t & 7;                    // lane within 8-lane point group
    int q   = t & 3;                    // channel quarter
    int hi  = (t >> 2) & 1;             // k parity handled by this lane
    int c0  = q << 2;
    int b   = p >> 15;                  // N = 2^15
    int n   = p & 32767;

    const float* xrow = x + b * NN;
    float xc = __ldg(xrow + n);         // 4 consecutive addrs per warp -> 1 line

    // per-thread folded constants for this quarter's 4 channels
    float A1h[4], D1h[4], Anh[4], Dnh[4], W2h[4], Wnh[4];
#pragma unroll
    for (int c = 0; c < 4; c++) {
        int cc = c0 + c;
        A1h[c] = sA1[cc];
        D1h[c] = fmaf(sB1[cc], xc, sC1[cc]);
        Anh[c] = sAn[cc];
        Dnh[c] = fmaf(sBn[cc], xc, sCn[cc]);
        W2h[c] = sW2[cc];
        Wnh[c] = sWn[cc];
    }
    float zc = sZC;

    // ---- own-k gathers, vector idx loads (dup addrs merge in-wavefront) ----
    // Lane's k at iteration kp is 2*kp+hi. xv[kp] holds its value; MLP = 10.
    float xv[10];
    if (g_idx_shift) {                  // int64: int4 j = elements {2j, 2j+1}
        const int4* ipb = (const int4*)(idx32 + (size_t)p * 40);
#pragma unroll
        for (int j = 0; j < 10; j++) {
            int4 w = __ldg(ipb + j);
            int id = hi ? w.z : w.x;    // low word of element 2j+hi
            xv[j] = __ldg(xrow + id);
        }
    } else {                            // int32: int4 j = elements {4j..4j+3}
        const int4* ipb = (const int4*)(idx32 + (size_t)p * 20);
#pragma unroll
        for (int j = 0; j < 5; j++) {
            int4 w = __ldg(ipb + j);
            int ia = hi ? w.y : w.x;    // kp=2j   -> k=4j+hi
            int ib = hi ? w.w : w.z;    // kp=2j+1 -> k=4j+2+hi
            xv[2*j]     = __ldg(xrow + ia);
            xv[2*j + 1] = __ldg(xrow + ib);
        }
    }

    float acc[4];
#pragma unroll
    for (int c = 0; c < 4; c++) acc[c] = 0.0f;
    float ssum = 0.0f;

    float* ep = edge_o + (size_t)p * (KK * CHN);   // this point's 1280B block

#pragma unroll
    for (int kp = 0; kp < KK / 2; kp++) {
        float d = xv[kp] - xc;

        float eo[4];
        float s = 0.0f;
#pragma unroll
        for (int c = 0; c < 4; c++) {
            float t1 = fmaf(A1h[c], d, D1h[c]);
            t1 = fmaxf(t1, 0.2f * t1);          // lrelu
            s  = fmaf(W2h[c], t1, s);
            float tn = fmaf(Anh[c], d, Dnh[c]);
            tn = fmaxf(tn, 0.2f * tn);
            eo[c] = tn;
            s  = fmaf(Wnh[c], tn, s);
        }
        // reduce the 4 quarters' partial logits (within the 4-lane k-subgroup)
        s += __shfl_xor_sync(0xffffffffu, s, 1);
        s += __shfl_xor_sync(0xffffffffu, s, 2);
        float z = zc + s;
        z = fmaxf(z, 0.2f * z);                 // lrelu(a+e)

        // fixed-shift softmax numerator
        float pk = exp2f(fmaf(z, L2E, -(ZSH * L2E)));
        ssum += pk;
#pragma unroll
        for (int c = 0; c < 4; c++)
            acc[c] = fmaf(pk, eo[c], acc[c]);

        // coalesced store: warp covers 4 points x 128B FULL lines
        __stcs((float4*)(ep + kp * 32 + l8 * 4), make_float4(eo[0], eo[1], eo[2], eo[3]));
    }

    // ---- combine the two k-parity halves (lane l <-> l^4) ----
    ssum += __shfl_xor_sync(0xffffffffu, ssum, 4);
#pragma unroll
    for (int c = 0; c < 4; c++)
        acc[c] += __shfl_xor_sync(0xffffffffu, acc[c], 4);

    if (hi == 0) {                      // lanes 0-3 of each group write 64B
        float inv = 1.0f / ssum;
        float* op = out + (size_t)p * CHN + c0;
        __stcs((float4*)op, make_float4(acc[0]*inv, acc[1]*inv, acc[2]*inv, acc[3]*inv));
    }
}

extern "C" void kernel_launch(void* const* d_in, const int* in_sizes, int n_in,
                              void* d_out, int out_size) {
    const float* x    = (const float*)d_in[0];
    // d_in[1] = pos (unused), d_in[3] = dis (unused)
    const int*   idx  = (const int*)d_in[2];
    const float* w1   = (const float*)d_in[4];
    const float* g1   = (const float*)d_in[5];
    const float* b1   = (const float*)d_in[6];
    const float* m1   = (const float*)d_in[7];
    const float* v1   = (const float*)d_in[8];
    const float* w2   = (const float*)d_in[9];
    const float* g2   = (const float*)d_in[10];
    const float* b2   = (const float*)d_in[11];
    const float* m2   = (const float*)d_in[12];
    const float* v2   = (const float*)d_in[13];
    const float* w1n  = (const float*)d_in[14];
    const float* g1n  = (const float*)d_in[15];
    const float* b1n  = (const float*)d_in[16];
    const float* m1n  = (const float*)d_in[17];
    const float* v1n  = (const float*)d_in[18];
    const float* w2n  = (const float*)d_in[19];
    const float* g2n  = (const float*)d_in[20];
    const float* b2n  = (const float*)d_in[21];
    const float* m2n  = (const float*)d_in[22];
    const float* v2n  = (const float*)d_in[23];

    float* out  = (float*)d_out;                         // (B,N,CH) first
    float* edge = out + (size_t)NPTS * CHN;              // then (B,N,K,CH)

    detect_idx_kernel<<<1, 128>>>((const unsigned int*)idx);
    // 8 lanes per point: NPTS*8 threads
    gap_kernel<<<(NPTS * 8) / 128, 128>>>(x, idx,
                                    w1, g1, b1, m1, v1, w2, g2, b2, m2, v2,
                                    w1n, g1n, b1n, m1n, v1n, w2n, g2n, b2n, m2n, v2n,
                                    out, edge);
}